// round 1
// baseline (speedup 1.0000x reference)
#include <cuda_runtime.h>
#include <cuda_fp16.h>
#include <cstdint>
#include <cstddef>

// Problem constants
#define S_ 2048
#define B_ 8
#define D_ 1024
#define E_ 8
#define H_ 512
#define T_ (S_*B_)        // 16384 tokens
#define N1_ (E_*H_)       // 4096 concatenated hidden

// ---------------------------------------------------------------------------
// Device scratch (allocation-free rule: static __device__ arrays)
// ---------------------------------------------------------------------------
__device__ __align__(128) __half g_xn [(size_t)T_*D_];    // 32 MB  LN output, fp16
__device__ __align__(128) __half g_hg [(size_t)T_*N1_];   // 128 MB gated hidden, fp16
__device__ __align__(128) __half g_w1h[(size_t)D_*N1_];   // 8 MB   W1cat [D, E*H]
__device__ __align__(128) __half g_w2h[(size_t)N1_*D_];   // 8 MB   W2cat [E*H, D]
__device__ float g_gates[B_*E_];
__device__ float g_b2g [B_*D_];                           // sum_e g[b,e]*b2[e,d]

// ---------------------------------------------------------------------------
// K0: masked max-pool -> gate logits -> softmax gates -> gate-weighted b2
// grid = B, block = 1024 (one thread per d)
// ---------------------------------------------------------------------------
__global__ void k_gate(const float* __restrict__ x, const unsigned char* __restrict__ pad,
                       const float* __restrict__ gw, const float* __restrict__ b2,
                       float* __restrict__ logits_out)
{
    const int b = blockIdx.x;
    const int d = threadIdx.x;   // 0..1023

    __shared__ unsigned char sp[S_];
    for (int s = d; s < S_; s += 1024) sp[s] = pad[b*S_ + s];
    __syncthreads();

    float m = -INFINITY;
    const float* xb = x + (size_t)b*D_ + d;
    #pragma unroll 4
    for (int s = 0; s < S_; ++s) {
        float v = xb[(size_t)s*(B_*D_)];
        if (sp[s]) v += -1e30f;
        m = fmaxf(m, v);
    }

    __shared__ float red[1024];
    __shared__ float slog[E_];
    __shared__ float sg[E_];
    for (int e = 0; e < E_; ++e) {
        red[d] = m * gw[e*D_ + d];
        __syncthreads();
        for (int off = 512; off > 0; off >>= 1) {
            if (d < off) red[d] += red[d + off];
            __syncthreads();
        }
        if (d == 0) slog[e] = red[0];
        __syncthreads();
    }

    if (d == 0) {
        float mx = -INFINITY;
        #pragma unroll
        for (int e = 0; e < E_; ++e) mx = fmaxf(mx, slog[e]);
        float ex[E_]; float sum = 0.f;
        #pragma unroll
        for (int e = 0; e < E_; ++e) { ex[e] = expf(slog[e] - mx); sum += ex[e]; }
        float t2 = 0.f;
        #pragma unroll
        for (int e = 0; e < E_; ++e) t2 += ex[e] / sum;
        #pragma unroll
        for (int e = 0; e < E_; ++e) {
            float g = (ex[e] / sum) / (t2 + 1e-9f);
            sg[e] = g;
            g_gates[b*E_ + e] = g;
            if (logits_out) logits_out[b*E_ + e] = slog[e];
        }
    }
    __syncthreads();

    float acc = 0.f;
    #pragma unroll
    for (int e = 0; e < E_; ++e) acc += sg[e] * b2[e*D_ + d];
    g_b2g[b*D_ + d] = acc;
}

// ---------------------------------------------------------------------------
// K1: LayerNorm (biased var, eps 1e-5) -> fp16  ; grid = T, block = 256
// ---------------------------------------------------------------------------
__global__ void k_ln(const float* __restrict__ x, const float* __restrict__ gamma,
                     const float* __restrict__ beta)
{
    const int t = blockIdx.x;
    const int tid = threadIdx.x;     // 256 threads, 4 floats each
    const float4 v = ((const float4*)(x + (size_t)t*D_))[tid];

    float s  = v.x + v.y + v.z + v.w;
    float ss = v.x*v.x + v.y*v.y + v.z*v.z + v.w*v.w;
    #pragma unroll
    for (int o = 16; o; o >>= 1) {
        s  += __shfl_xor_sync(0xffffffffu, s,  o);
        ss += __shfl_xor_sync(0xffffffffu, ss, o);
    }
    __shared__ float rs[8], rss[8];
    if ((tid & 31) == 0) { rs[tid>>5] = s; rss[tid>>5] = ss; }
    __syncthreads();
    s = 0.f; ss = 0.f;
    #pragma unroll
    for (int w = 0; w < 8; ++w) { s += rs[w]; ss += rss[w]; }

    const float mu  = s * (1.0f / D_);
    const float var = ss * (1.0f / D_) - mu*mu;
    const float inv = rsqrtf(var + 1e-5f);

    const float4 gm = ((const float4*)gamma)[tid];
    const float4 bt = ((const float4*)beta )[tid];
    float o0 = (v.x - mu)*inv*gm.x + bt.x;
    float o1 = (v.y - mu)*inv*gm.y + bt.y;
    float o2 = (v.z - mu)*inv*gm.z + bt.z;
    float o3 = (v.w - mu)*inv*gm.w + bt.w;

    __half2* dst = (__half2*)(g_xn + (size_t)t*D_ + tid*4);
    dst[0] = __floats2half2_rn(o0, o1);
    dst[1] = __floats2half2_rn(o2, o3);
}

// ---------------------------------------------------------------------------
// K2: weight conversion fp32 -> fp16 (re-layout W1 to [D, E*H]; W2 already flat)
// ---------------------------------------------------------------------------
__global__ void k_wconv(const float* __restrict__ w1, const float* __restrict__ w2)
{
    const size_t i = (size_t)blockIdx.x * blockDim.x + threadIdx.x;
    if (i < (size_t)D_*N1_) {
        const int d = (int)(i >> 12);
        const int j = (int)(i & 4095);
        const int e = j >> 9;
        const int h = j & 511;
        g_w1h[i] = __float2half(w1[((size_t)e << 19) + ((size_t)d << 9) + h]);
    } else {
        const size_t k = i - (size_t)D_*N1_;
        g_w2h[k] = __float2half(w2[k]);
    }
}

// ---------------------------------------------------------------------------
// GEMM plumbing: mma.sync fp16, 128x128x32 tiles, cp.async double-buffer
// ---------------------------------------------------------------------------
__device__ __forceinline__ void ldsm4(uint32_t& r0, uint32_t& r1, uint32_t& r2, uint32_t& r3, uint32_t a) {
    asm volatile("ldmatrix.sync.aligned.m8n8.x4.shared.b16 {%0,%1,%2,%3},[%4];"
                 : "=r"(r0), "=r"(r1), "=r"(r2), "=r"(r3) : "r"(a));
}
__device__ __forceinline__ void ldsm4t(uint32_t& r0, uint32_t& r1, uint32_t& r2, uint32_t& r3, uint32_t a) {
    asm volatile("ldmatrix.sync.aligned.m8n8.x4.trans.shared.b16 {%0,%1,%2,%3},[%4];"
                 : "=r"(r0), "=r"(r1), "=r"(r2), "=r"(r3) : "r"(a));
}
__device__ __forceinline__ void cpa16(uint32_t d, const void* s) {
    asm volatile("cp.async.cg.shared.global [%0],[%1],16;" :: "r"(d), "l"(s));
}
__device__ __forceinline__ void mma_(float* d, const uint32_t* a, const uint32_t* b) {
    asm volatile("mma.sync.aligned.m16n8k16.row.col.f32.f16.f16.f32 "
                 "{%0,%1,%2,%3},{%4,%5,%6,%7},{%8,%9},{%0,%1,%2,%3};"
                 : "+f"(d[0]), "+f"(d[1]), "+f"(d[2]), "+f"(d[3])
                 : "r"(a[0]), "r"(a[1]), "r"(a[2]), "r"(a[3]), "r"(b[0]), "r"(b[1]));
}

// EPI1: relu(acc+b1)*gate -> g_hg (fp16).  EPI2: acc + x + b2g -> out (fp32).
template<int M, int N, int K, bool EPI1>
__global__ void __launch_bounds__(256)
k_gemm(const float* __restrict__ b1, const float* __restrict__ xres, float* __restrict__ out)
{
    constexpr int BM = 128, BN = 128, BK = 32;
    constexpr int LDA = 40;   // 128x32 tile, pad to 40 halfs/row (80B): conflict-free ldmatrix
    constexpr int LDB = 136;  // 32x128 tile, pad to 136 halfs/row (272B)
    constexpr int KT = K / BK;

    __shared__ __align__(128) __half sA[2][BM*LDA];
    __shared__ __align__(128) __half sB[2][BK*LDB];
    __shared__ float sgates[B_*E_];

    const __half* __restrict__ A  = EPI1 ? g_xn  : g_hg;
    const __half* __restrict__ Bm = EPI1 ? g_w1h : g_w2h;

    const int tid  = threadIdx.x;
    const int lane = tid & 31;
    const int warp = tid >> 5;
    const int wm = warp >> 1;          // 0..3  (M direction, 32 rows each)
    const int wn = warp & 1;           // 0..1  (N direction, 64 cols each)
    const int bm = blockIdx.y * BM;
    const int bn = blockIdx.x * BN;

    if (EPI1 && tid < B_*E_) sgates[tid] = g_gates[tid];

    float acc[2][8][4];
    #pragma unroll
    for (int i = 0; i < 2; ++i)
        #pragma unroll
        for (int j = 0; j < 8; ++j)
            #pragma unroll
            for (int p = 0; p < 4; ++p) acc[i][j][p] = 0.f;

    auto load_stage = [&](int st, int k0) {
        uint32_t sa = (uint32_t)__cvta_generic_to_shared(&sA[st][0]);
        uint32_t sb = (uint32_t)__cvta_generic_to_shared(&sB[st][0]);
        #pragma unroll
        for (int t = 0; t < 2; ++t) {            // A: 128 rows x 4 chunks(16B)
            int q = tid + t*256;
            int r = q >> 2, c = q & 3;
            cpa16(sa + (uint32_t)(r*LDA + c*8)*2, A + (size_t)(bm + r)*K + k0 + c*8);
        }
        #pragma unroll
        for (int t = 0; t < 2; ++t) {            // B: 32 rows x 16 chunks(16B)
            int q = tid + t*256;
            int r = q >> 4, c = q & 15;
            cpa16(sb + (uint32_t)(r*LDB + c*8)*2, Bm + (size_t)(k0 + r)*N + bn + c*8);
        }
        asm volatile("cp.async.commit_group;");
    };

    auto compute_stage = [&](int st) {
        uint32_t abase = (uint32_t)__cvta_generic_to_shared(&sA[st][0]);
        uint32_t bbase = (uint32_t)__cvta_generic_to_shared(&sB[st][0]);
        #pragma unroll
        for (int ks = 0; ks < 2; ++ks) {
            const int k0 = ks * 16;
            uint32_t af[2][4], bf[8][2];
            #pragma unroll
            for (int i = 0; i < 2; ++i) {
                int row = wm*32 + i*16 + (lane & 15);
                int col = k0 + ((lane >> 4) << 3);
                ldsm4(af[i][0], af[i][1], af[i][2], af[i][3],
                      abase + (uint32_t)(row*LDA + col)*2);
            }
            #pragma unroll
            for (int jj = 0; jj < 4; ++jj) {     // each covers 16 N-cols => 2 n8 tiles
                int kr  = k0 + (lane & 15);
                int col = wn*64 + jj*16 + ((lane >> 4) << 3);
                ldsm4t(bf[2*jj][0], bf[2*jj][1], bf[2*jj+1][0], bf[2*jj+1][1],
                       bbase + (uint32_t)(kr*LDB + col)*2);
            }
            #pragma unroll
            for (int i = 0; i < 2; ++i)
                #pragma unroll
                for (int j = 0; j < 8; ++j)
                    mma_(acc[i][j], af[i], bf[j]);
        }
    };

    load_stage(0, 0);
    for (int it = 0; it < KT; ++it) {
        if (it + 1 < KT) {
            load_stage((it + 1) & 1, (it + 1)*BK);
            asm volatile("cp.async.wait_group 1;");
        } else {
            asm volatile("cp.async.wait_group 0;");
        }
        __syncthreads();
        compute_stage(it & 1);
        __syncthreads();
    }

    const int g  = lane >> 2;
    const int tc = lane & 3;
    if (EPI1) {
        #pragma unroll
        for (int i = 0; i < 2; ++i) {
            #pragma unroll
            for (int j = 0; j < 8; ++j) {
                const int col = bn + wn*64 + j*8 + tc*2;
                const int e = col >> 9;               // expert of this column
                const float bb0 = b1[col], bb1 = b1[col + 1];
                #pragma unroll
                for (int p = 0; p < 2; ++p) {
                    const int row = bm + wm*32 + i*16 + g + p*8;
                    const float gsc = sgates[(row & 7)*E_ + e];
                    float v0 = fmaxf(acc[i][j][2*p+0] + bb0, 0.f) * gsc;
                    float v1 = fmaxf(acc[i][j][2*p+1] + bb1, 0.f) * gsc;
                    *reinterpret_cast<__half2*>(&g_hg[(size_t)row*N1_ + col]) =
                        __floats2half2_rn(v0, v1);
                }
            }
        }
    } else {
        #pragma unroll
        for (int i = 0; i < 2; ++i) {
            #pragma unroll
            for (int j = 0; j < 8; ++j) {
                const int col = bn + wn*64 + j*8 + tc*2;
                #pragma unroll
                for (int p = 0; p < 2; ++p) {
                    const int row = bm + wm*32 + i*16 + g + p*8;
                    const size_t o = (size_t)row*D_ + col;
                    const int bo = (row & 7)*D_ + col;
                    float2 r;
                    r.x = acc[i][j][2*p+0] + xres[o]     + g_b2g[bo];
                    r.y = acc[i][j][2*p+1] + xres[o + 1] + g_b2g[bo + 1];
                    *reinterpret_cast<float2*>(&out[o]) = r;
                }
            }
        }
    }
}

// ---------------------------------------------------------------------------
// Launch
// ---------------------------------------------------------------------------
extern "C" void kernel_launch(void* const* d_in, const int* in_sizes, int n_in,
                              void* d_out, int out_size)
{
    const float*         x   = (const float*)d_in[0];
    const unsigned char* pad = (const unsigned char*)d_in[1];
    const float*         gw  = (const float*)d_in[2];
    const float*         lng = (const float*)d_in[3];
    const float*         lnb = (const float*)d_in[4];
    const float*         w1  = (const float*)d_in[5];
    const float*         b1  = (const float*)d_in[6];
    const float*         w2  = (const float*)d_in[7];
    const float*         b2  = (const float*)d_in[8];
    float* out = (float*)d_out;

    float* logits_dst = (out_size >= T_*D_ + B_*E_) ? (out + (size_t)T_*D_) : nullptr;

    k_gate <<<B_, 1024>>>(x, pad, gw, b2, logits_dst);
    k_ln   <<<T_, 256>>>(x, lng, lnb);
    k_wconv<<<(2*D_*N1_)/256, 256>>>(w1, w2);

    // GEMM1: XN[16384,1024] @ W1cat[1024,4096] -> g_hg (relu, +b1, *gate)
    k_gemm<T_, N1_, D_, true ><<<dim3(N1_/128, T_/128), 256>>>(b1, nullptr, nullptr);
    // GEMM2: g_hg[16384,4096] @ W2cat[4096,1024] + x + b2g -> out
    k_gemm<T_, D_, N1_, false><<<dim3(D_/128, T_/128), 256>>>(nullptr, x, out);
}

// round 4
// speedup vs baseline: 1.1227x; 1.1227x over previous
#include <cuda_runtime.h>
#include <cuda_fp16.h>
#include <cstdint>
#include <cstddef>

// Problem constants
#define S_ 2048
#define B_ 8
#define D_ 1024
#define E_ 8
#define H_ 512
#define T_ (S_*B_)        // 16384 tokens
#define N1_ (E_*H_)       // 4096 concatenated hidden

// ---------------------------------------------------------------------------
// Device scratch
// ---------------------------------------------------------------------------
__device__ __align__(128) __half g_xn [(size_t)T_*D_];    // LN output fp16 [T, D]
__device__ __align__(128) __half g_hg [(size_t)T_*N1_];   // gated hidden fp16 [T, N1]
__device__ __align__(128) __half g_w1h[(size_t)D_*N1_];   // W1cat [D, E*H]  ([K,N] row-major)
__device__ __align__(128) __half g_w2h[(size_t)N1_*D_];   // W2cat [E*H, D]  ([K,N] row-major)
__device__ float g_gates[B_*E_];
__device__ float g_b2g [B_*D_];
__device__ float g_pmax[B_*32*D_];

// ---------------------------------------------------------------------------
// K0a: partial masked max-pool.  grid (32, B), block 1024
// ---------------------------------------------------------------------------
__global__ void k_pool(const float* __restrict__ x, const unsigned char* __restrict__ pad)
{
    const int b = blockIdx.y, ch = blockIdx.x, d = threadIdx.x;
    const int s0 = ch * 64;
    float m = -INFINITY;
    #pragma unroll 4
    for (int i = 0; i < 64; ++i) {
        const int s = s0 + i;
        float v = x[((size_t)s*B_ + b)*D_ + d];
        if (pad[b*S_ + s]) v += -1e30f;
        m = fmaxf(m, v);
    }
    g_pmax[((b*32 + ch) << 10) + d] = m;
}

// ---------------------------------------------------------------------------
// K0b: reduce partials -> logits -> gates -> gate-weighted b2.  grid B, block 1024
// ---------------------------------------------------------------------------
__global__ void k_gate2(const float* __restrict__ gw, const float* __restrict__ b2,
                        float* __restrict__ logits_out)
{
    const int b = blockIdx.x, d = threadIdx.x;
    float m = -INFINITY;
    #pragma unroll
    for (int c = 0; c < 32; ++c) m = fmaxf(m, g_pmax[((b*32 + c) << 10) + d]);

    __shared__ float red[1024];
    __shared__ float slog[E_];
    __shared__ float sg[E_];
    for (int e = 0; e < E_; ++e) {
        red[d] = m * gw[e*D_ + d];
        __syncthreads();
        for (int off = 512; off > 0; off >>= 1) {
            if (d < off) red[d] += red[d + off];
            __syncthreads();
        }
        if (d == 0) slog[e] = red[0];
        __syncthreads();
    }

    if (d == 0) {
        float mx = -INFINITY;
        #pragma unroll
        for (int e = 0; e < E_; ++e) mx = fmaxf(mx, slog[e]);
        float ex[E_]; float sum = 0.f;
        #pragma unroll
        for (int e = 0; e < E_; ++e) { ex[e] = expf(slog[e] - mx); sum += ex[e]; }
        float t2 = 0.f;
        #pragma unroll
        for (int e = 0; e < E_; ++e) t2 += ex[e] / sum;
        #pragma unroll
        for (int e = 0; e < E_; ++e) {
            float g = (ex[e] / sum) / (t2 + 1e-9f);
            sg[e] = g;
            g_gates[b*E_ + e] = g;
            if (logits_out) logits_out[b*E_ + e] = slog[e];
        }
    }
    __syncthreads();

    float acc = 0.f;
    #pragma unroll
    for (int e = 0; e < E_; ++e) acc += sg[e] * b2[e*D_ + d];
    g_b2g[b*D_ + d] = acc;
}

// ---------------------------------------------------------------------------
// K1: LayerNorm -> fp16.  grid T, block 256
// ---------------------------------------------------------------------------
__global__ void k_ln(const float* __restrict__ x, const float* __restrict__ gamma,
                     const float* __restrict__ beta)
{
    const int t = blockIdx.x;
    const int tid = threadIdx.x;
    const float4 v = ((const float4*)(x + (size_t)t*D_))[tid];

    float s  = v.x + v.y + v.z + v.w;
    float ss = v.x*v.x + v.y*v.y + v.z*v.z + v.w*v.w;
    #pragma unroll
    for (int o = 16; o; o >>= 1) {
        s  += __shfl_xor_sync(0xffffffffu, s,  o);
        ss += __shfl_xor_sync(0xffffffffu, ss, o);
    }
    __shared__ float rs[8], rss[8];
    if ((tid & 31) == 0) { rs[tid>>5] = s; rss[tid>>5] = ss; }
    __syncthreads();
    s = 0.f; ss = 0.f;
    #pragma unroll
    for (int w = 0; w < 8; ++w) { s += rs[w]; ss += rss[w]; }

    const float mu  = s * (1.0f / D_);
    const float var = ss * (1.0f / D_) - mu*mu;
    const float inv = rsqrtf(var + 1e-5f);

    const float4 gm = ((const float4*)gamma)[tid];
    const float4 bt = ((const float4*)beta )[tid];
    __half2* dst = (__half2*)(g_xn + (size_t)t*D_ + tid*4);
    dst[0] = __floats2half2_rn((v.x - mu)*inv*gm.x + bt.x, (v.y - mu)*inv*gm.y + bt.y);
    dst[1] = __floats2half2_rn((v.z - mu)*inv*gm.z + bt.z, (v.w - mu)*inv*gm.w + bt.w);
}

// ---------------------------------------------------------------------------
// K2: weight conversion fp32 -> fp16 (both sides coalesced in h / d)
// g_w1h[d*4096 + e*512 + h] = w1[e][d][h] ;  g_w2h = flat copy of w2
// ---------------------------------------------------------------------------
__global__ void k_wconv(const float* __restrict__ w1, const float* __restrict__ w2)
{
    const size_t i = (size_t)blockIdx.x * blockDim.x + threadIdx.x;
    if (i < (size_t)D_*N1_) {
        const int d = (int)(i >> 12);
        const int j = (int)(i & 4095);
        const int e = j >> 9;
        const int h = j & 511;
        g_w1h[i] = __float2half(w1[((size_t)e << 19) + ((size_t)d << 9) + h]);
    } else {
        const size_t k = i - (size_t)D_*N1_;
        g_w2h[k] = __float2half(w2[k]);
    }
}

// ---------------------------------------------------------------------------
// mma.sync GEMM: 128x256x32 CTA tile, 8 warps, 64x64 warp tile,
// 4-stage cp.async pipeline, padded conflict-free smem.
// ---------------------------------------------------------------------------
__device__ __forceinline__ void ldsm4(uint32_t* r, uint32_t a) {
    asm volatile("ldmatrix.sync.aligned.m8n8.x4.shared.b16 {%0,%1,%2,%3},[%4];"
                 : "=r"(r[0]), "=r"(r[1]), "=r"(r[2]), "=r"(r[3]) : "r"(a));
}
__device__ __forceinline__ void ldsm4t(uint32_t& r0, uint32_t& r1, uint32_t& r2, uint32_t& r3, uint32_t a) {
    asm volatile("ldmatrix.sync.aligned.m8n8.x4.trans.shared.b16 {%0,%1,%2,%3},[%4];"
                 : "=r"(r0), "=r"(r1), "=r"(r2), "=r"(r3) : "r"(a));
}
__device__ __forceinline__ void cpa16(uint32_t d, const void* s) {
    asm volatile("cp.async.cg.shared.global [%0],[%1],16;" :: "r"(d), "l"(s));
}
__device__ __forceinline__ void mma_(float* d, const uint32_t* a, const uint32_t* b) {
    asm volatile("mma.sync.aligned.m16n8k16.row.col.f32.f16.f16.f32 "
                 "{%0,%1,%2,%3},{%4,%5,%6,%7},{%8,%9},{%0,%1,%2,%3};"
                 : "+f"(d[0]), "+f"(d[1]), "+f"(d[2]), "+f"(d[3])
                 : "r"(a[0]), "r"(a[1]), "r"(a[2]), "r"(a[3]), "r"(b[0]), "r"(b[1]));
}

#define LDA_ 40            // halfs per A row  (128x32 tile)
#define LDB_ 264           // halfs per B row  (32x256 tile)
#define ASTG (128*LDA_*2)  // 10240 B
#define BSTG (32*LDB_*2)   // 16896 B
#define NSTAGE 4
#define GSMEM_SZ (NSTAGE*(ASTG+BSTG))

template<int N_TOT, int K, bool EPI1>
__global__ void __launch_bounds__(256)
k_gemm(const float* __restrict__ b1, const float* __restrict__ xres, float* __restrict__ out)
{
    constexpr int KT = K / 32;

    extern __shared__ __align__(128) char dsm[];
    __half* sA = (__half*)dsm;                       // NSTAGE x 128 x LDA_
    __half* sB = (__half*)(dsm + NSTAGE*ASTG);       // NSTAGE x 32  x LDB_

    const __half* __restrict__ A  = EPI1 ? g_xn  : g_hg;
    const __half* __restrict__ Bm = EPI1 ? g_w1h : g_w2h;

    const int tid  = threadIdx.x;
    const int lane = tid & 31;
    const int warp = tid >> 5;
    const int wm = warp >> 2;          // 0..1  (M, 64 rows each)
    const int wn = warp & 3;           // 0..3  (N, 64 cols each)
    const int bm = blockIdx.y * 128;
    const int bn = blockIdx.x * 256;

    float acc[4][8][4];
    #pragma unroll
    for (int i = 0; i < 4; ++i)
        #pragma unroll
        for (int j = 0; j < 8; ++j)
            #pragma unroll
            for (int p = 0; p < 4; ++p) acc[i][j][p] = 0.f;

    const uint32_t sab = (uint32_t)__cvta_generic_to_shared(sA);
    const uint32_t sbb = (uint32_t)__cvta_generic_to_shared(sB);

    auto load_stage = [&](int st, int k0) {
        const uint32_t sa = sab + st*ASTG;
        const uint32_t sb = sbb + st*BSTG;
        #pragma unroll
        for (int t = 0; t < 2; ++t) {            // A: 128 rows x 4 chunks(16B)
            int q = tid + t*256;
            int r = q >> 2, c = q & 3;
            cpa16(sa + (uint32_t)(r*LDA_ + c*8)*2, A + (size_t)(bm + r)*K + k0 + c*8);
        }
        #pragma unroll
        for (int t = 0; t < 4; ++t) {            // B: 32 rows x 32 chunks(16B)
            int q = tid + t*256;
            int r = q >> 5, c = q & 31;
            cpa16(sb + (uint32_t)(r*LDB_ + c*8)*2, Bm + (size_t)(k0 + r)*N_TOT + bn + c*8);
        }
        asm volatile("cp.async.commit_group;");
    };

    auto compute_stage = [&](int st) {
        const uint32_t abase = sab + st*ASTG;
        const uint32_t bbase = sbb + st*BSTG;
        #pragma unroll
        for (int ks = 0; ks < 2; ++ks) {
            const int k0 = ks * 16;
            uint32_t af[4][4], bf[8][2];
            #pragma unroll
            for (int i = 0; i < 4; ++i) {
                int row = wm*64 + i*16 + (lane & 15);
                int col = k0 + ((lane >> 4) << 3);
                ldsm4(af[i], abase + (uint32_t)(row*LDA_ + col)*2);
            }
            #pragma unroll
            for (int jj = 0; jj < 4; ++jj) {
                int kr  = k0 + (lane & 15);
                int col = wn*64 + jj*16 + ((lane >> 4) << 3);
                ldsm4t(bf[2*jj][0], bf[2*jj][1], bf[2*jj+1][0], bf[2*jj+1][1],
                       bbase + (uint32_t)(kr*LDB_ + col)*2);
            }
            #pragma unroll
            for (int i = 0; i < 4; ++i)
                #pragma unroll
                for (int j = 0; j < 8; ++j)
                    mma_(acc[i][j], af[i], bf[j]);
        }
    };

    load_stage(0, 0);
    load_stage(1, 32);
    load_stage(2, 64);
    for (int it = 0; it < KT; ++it) {
        asm volatile("cp.async.wait_group 2;");
        __syncthreads();
        if (it + 3 < KT) load_stage((it + 3) & (NSTAGE - 1), (it + 3)*32);
        else             asm volatile("cp.async.commit_group;");
        compute_stage(it & (NSTAGE - 1));
    }

    // ---- epilogue ----
    const int g  = lane >> 2;
    const int tc = lane & 3;
    if (EPI1) {
        #pragma unroll
        for (int i = 0; i < 4; ++i) {
            #pragma unroll
            for (int j = 0; j < 8; ++j) {
                const int col = bn + wn*64 + j*8 + tc*2;
                const int e = col >> 9;
                const float bb0 = __ldg(&b1[col]), bb1 = __ldg(&b1[col + 1]);
                #pragma unroll
                for (int p = 0; p < 2; ++p) {
                    const int row = bm + wm*64 + i*16 + g + p*8;
                    const float gsc = g_gates[((row & 7) << 3) + e];
                    float v0 = fmaxf(acc[i][j][2*p+0] + bb0, 0.f) * gsc;
                    float v1 = fmaxf(acc[i][j][2*p+1] + bb1, 0.f) * gsc;
                    *reinterpret_cast<__half2*>(&g_hg[(size_t)row*N1_ + col]) =
                        __floats2half2_rn(v0, v1);
                }
            }
        }
    } else {
        #pragma unroll
        for (int i = 0; i < 4; ++i) {
            #pragma unroll
            for (int j = 0; j < 8; ++j) {
                const int col = bn + wn*64 + j*8 + tc*2;
                #pragma unroll
                for (int p = 0; p < 2; ++p) {
                    const int row = bm + wm*64 + i*16 + g + p*8;
                    const size_t o = (size_t)row*D_ + col;
                    const int bo = (row & 7)*D_ + col;
                    float2 r;
                    r.x = acc[i][j][2*p+0] + xres[o]     + g_b2g[bo];
                    r.y = acc[i][j][2*p+1] + xres[o + 1] + g_b2g[bo + 1];
                    *reinterpret_cast<float2*>(&out[o]) = r;
                }
            }
        }
    }
}

// ---------------------------------------------------------------------------
// Launch
// ---------------------------------------------------------------------------
extern "C" void kernel_launch(void* const* d_in, const int* in_sizes, int n_in,
                              void* d_out, int out_size)
{
    const float*         x   = (const float*)d_in[0];
    const unsigned char* pad = (const unsigned char*)d_in[1];
    const float*         gw  = (const float*)d_in[2];
    const float*         lng = (const float*)d_in[3];
    const float*         lnb = (const float*)d_in[4];
    const float*         w1  = (const float*)d_in[5];
    const float*         b1  = (const float*)d_in[6];
    const float*         w2  = (const float*)d_in[7];
    const float*         b2  = (const float*)d_in[8];
    float* out = (float*)d_out;

    float* logits_dst = (out_size >= T_*D_ + B_*E_) ? (out + (size_t)T_*D_) : nullptr;

    static bool attr_done = false;
    if (!attr_done) {
        cudaFuncSetAttribute(k_gemm<N1_, D_,  true >, cudaFuncAttributeMaxDynamicSharedMemorySize, GSMEM_SZ);
        cudaFuncSetAttribute(k_gemm<D_,  N1_, false>, cudaFuncAttributeMaxDynamicSharedMemorySize, GSMEM_SZ);
        attr_done = true;
    }

    k_pool <<<dim3(32, B_), 1024>>>(x, pad);
    k_gate2<<<B_, 1024>>>(gw, b2, logits_dst);
    k_ln   <<<T_, 256>>>(x, lng, lnb);
    k_wconv<<<(2*D_*N1_)/256, 256>>>(w1, w2);

    // GEMM1: XN[16384,1024] @ W1cat[1024,4096] -> g_hg (relu, +b1, *gate)
    k_gemm<N1_, D_,  true ><<<dim3(N1_/256, T_/128), 256, GSMEM_SZ>>>(b1, nullptr, nullptr);
    // GEMM2: HG[16384,4096] @ W2cat[4096,1024] + x + b2g -> out
    k_gemm<D_,  N1_, false><<<dim3(D_/256,  T_/128), 256, GSMEM_SZ>>>(nullptr, x, out);
}